// round 16
// baseline (speedup 1.0000x reference)
#include <cuda_runtime.h>
#include <cuda_bf16.h>

#define NA   400000
#define NG   64
#define CAP  32768
#define TOPK 10
#define TBS  256

// Scratch (device globals: no allocations allowed anywhere).
__device__ int   g_count[NG];
__device__ float g_thresh[NG];
__device__ float g_val[NG * CAP];
__device__ int   g_anc[NG * CAP];
__device__ int   g_best[NA];
__device__ int   g_fg[NA];

// K0: reset per-GT candidate counters (graph replays reuse globals).
__global__ void k_zero() {
    if (threadIdx.x < NG) g_count[threadIdx.x] = 0;
}

// K1: main pass. One thread per anchor: 64-bit in-box mask via smem-broadcast
// compares, then sparse IoU/metric only on set bits (~0.8 per anchor).
__global__ void __launch_bounds__(TBS) k_main(
    const float*  __restrict__ scores,   // [NA]      (NUM_CLASSES == 1)
    const float4* __restrict__ pboxes,   // [NA]      (x0,y0,x1,y1)
    const float2* __restrict__ anc,      // [NA]      (x,y)
    const float4* __restrict__ gtb)      // [NG]      (x0,y0,x1,y1)
{
    __shared__ float4 s_gt[NG];
    __shared__ float  s_area[NG];
    const int tid = threadIdx.x;
    if (tid < NG) {
        float4 bx = gtb[tid];
        s_gt[tid]   = bx;
        s_area[tid] = (bx.z - bx.x) * (bx.w - bx.y);
    }
    __syncthreads();

    const int a = blockIdx.x * blockDim.x + tid;
    if (a >= NA) return;

    const float2 p   = anc[a];
    const float4 pbx = pboxes[a];
    const float  area1 = (pbx.z - pbx.x) * (pbx.w - pbx.y);
    const float  s0 = scores[a];

    unsigned long long mask = 0ull;
#pragma unroll
    for (int g = 0; g < NG; ++g) {
        float4 bx = s_gt[g];
        bool in = (p.x >= bx.x) && (p.x <= bx.z) && (p.y >= bx.y) && (p.y <= bx.w);
        if (in) mask |= (1ull << g);
    }

    float best = 0.f;
    int bestg = 0;                         // argmax of an all-zero row -> 0
    while (mask) {
        const int g = __ffsll((long long)mask) - 1;   // ascending g: first-max tie rule
        mask &= mask - 1ull;
        const float4 bx = s_gt[g];
        float lx = fmaxf(pbx.x, bx.x);
        float ly = fmaxf(pbx.y, bx.y);
        float rx = fminf(pbx.z, bx.z);
        float ry = fminf(pbx.w, bx.w);
        float w  = fmaxf(rx - lx, 0.f);
        float h  = fmaxf(ry - ly, 0.f);
        float inter = w * h;
        float iou = inter / (area1 + s_area[g] - inter);
        float i2  = iou * iou;
        float v   = s0 * (i2 * i2 * i2);   // cls^1 * iou^6
        if (v > best) { best = v; bestg = g; }
        if (v > 0.f) {
            int pos = atomicAdd(&g_count[g], 1);
            if (pos < CAP) {
                g_val[g * CAP + pos] = v;
                g_anc[g * CAP + pos] = a;
            }
        }
    }
    g_best[a] = bestg;
    g_fg[a]   = 0;                         // reset for K3
}

// K2: one block per GT -> 10th-largest candidate value becomes the threshold.
__global__ void __launch_bounds__(TBS) k_thresh() {
    const int g   = blockIdx.x;
    const int c   = min(g_count[g], CAP);
    const int tid = threadIdx.x;

    float t[TOPK];
#pragma unroll
    for (int i = 0; i < TOPK; ++i) t[i] = 0.f;

    for (int i = tid; i < c; i += TBS) {
        float v = g_val[g * CAP + i];
        if (v > t[0]) {
            t[0] = v;
#pragma unroll
            for (int k = 0; k < TOPK - 1; ++k) {
                if (t[k] > t[k + 1]) { float tmp = t[k]; t[k] = t[k + 1]; t[k + 1] = tmp; }
                else break;
            }
        }
    }

    __shared__ float sv[TBS * TOPK];
#pragma unroll
    for (int i = 0; i < TOPK; ++i) sv[tid * TOPK + i] = t[i];
    __syncthreads();

    for (int stride = TBS / 2; stride >= 1; stride >>= 1) {
        if (tid < stride) {
            float o[TOPK];
#pragma unroll
            for (int i = 0; i < TOPK; ++i) o[i] = sv[(tid + stride) * TOPK + i];
            float m[TOPK];
            int ti = TOPK - 1, oi = TOPK - 1;
#pragma unroll
            for (int k = TOPK - 1; k >= 0; --k) {
                float tv = (ti >= 0) ? t[ti] : -1.f;
                float ov = (oi >= 0) ? o[oi] : -1.f;
                if (tv >= ov) { m[k] = tv; --ti; }
                else          { m[k] = ov; --oi; }
            }
#pragma unroll
            for (int i = 0; i < TOPK; ++i) { t[i] = m[i]; sv[tid * TOPK + i] = m[i]; }
        }
        __syncthreads();
    }
    if (tid == 0) g_thresh[g] = t[0];      // 10th largest (0 if fewer than 10 positives)
}

// K3: mark fg anchors (all stored candidates are > 0, so >= thresh is the top-k set).
__global__ void __launch_bounds__(TBS) k_mark() {
    const int g = blockIdx.y;
    const int c = min(g_count[g], CAP);
    const float th = g_thresh[g];
    for (int i = blockIdx.x * blockDim.x + threadIdx.x; i < c;
         i += gridDim.x * blockDim.x) {
        if (g_val[g * CAP + i] >= th) g_fg[g_anc[g * CAP + i]] = 1;
    }
}

// K4: float32 output. out[0..A) = fg_mask as 0.0/1.0, out[A..2A) = argmax idx.
__global__ void __launch_bounds__(TBS) k_final(float* __restrict__ out, int write_idx) {
    const int a = blockIdx.x * blockDim.x + threadIdx.x;
    if (a >= NA) return;
    const int fg = g_fg[a];
    out[a] = fg ? 1.0f : 0.0f;
    if (write_idx) out[NA + a] = (float)(fg ? g_best[a] : 0);
}

extern "C" void kernel_launch(void* const* d_in, const int* in_sizes, int n_in,
                              void* d_out, int out_size) {
    // Bind inputs BY ELEMENT COUNT on the host — the five sizes are pairwise
    // distinct (400000 / 1600000 / 800000 / 64 / 256), so this is ordering-proof
    // and costs zero device work (the 246us run proved binding was never the
    // failure; the single-threaded device-side sniffer was pure overhead).
    const float*  scores = nullptr;
    const float4* pboxes = nullptr;
    const float2* anc    = nullptr;
    const float4* gtb    = nullptr;
    for (int i = 0; i < n_in; ++i) {
        switch (in_sizes[i]) {
            case NA:     scores = (const float*)d_in[i];  break;
            case NA * 4: pboxes = (const float4*)d_in[i]; break;
            case NA * 2: anc    = (const float2*)d_in[i]; break;
            case NG * 4: gtb    = (const float4*)d_in[i]; break;
            default: break;   // gt_labels (NG) unused: NUM_CLASSES == 1
        }
    }
    const int write_idx = (out_size >= 2 * NA) ? 1 : 0;

    k_zero  <<<1, 64>>>();
    k_main  <<<(NA + TBS - 1) / TBS, TBS>>>(scores, pboxes, anc, gtb);
    k_thresh<<<NG, TBS>>>();
    k_mark  <<<dim3(8, NG), TBS>>>();
    k_final <<<(NA + TBS - 1) / TBS, TBS>>>((float*)d_out, write_idx);
}

// round 17
// speedup vs baseline: 1.0083x; 1.0083x over previous
#include <cuda_runtime.h>
#include <cuda_bf16.h>

#define NA   400000
#define NG   64
#define CAP  32768
#define TOPK 10
#define TBS  256

// Scratch (device globals: no allocations allowed anywhere).
__device__ int   g_count[NG];
__device__ float g_thresh[NG];
__device__ float g_val[NG * CAP];
__device__ int   g_anc[NG * CAP];
__device__ int   g_best[NA];
__device__ int   g_fg[NA];

// K0: reset per-GT candidate counters (graph replays reuse globals).
__global__ void k_zero() {
    if (threadIdx.x < NG) g_count[threadIdx.x] = 0;
}

// K1: main pass. One thread per anchor: 64-bit in-box mask via smem-broadcast
// compares, then sparse IoU/metric only on set bits (~0.8 per anchor).
__global__ void __launch_bounds__(TBS) k_main(
    const float*  __restrict__ scores,   // [NA]      (NUM_CLASSES == 1)
    const float4* __restrict__ pboxes,   // [NA]      (x0,y0,x1,y1)
    const float2* __restrict__ anc,      // [NA]      (x,y)
    const float4* __restrict__ gtb)      // [NG]      (x0,y0,x1,y1)
{
    __shared__ float4 s_gt[NG];
    __shared__ float  s_area[NG];
    const int tid = threadIdx.x;
    if (tid < NG) {
        float4 bx = gtb[tid];
        s_gt[tid]   = bx;
        s_area[tid] = (bx.z - bx.x) * (bx.w - bx.y);
    }
    __syncthreads();

    const int a = blockIdx.x * blockDim.x + tid;
    if (a >= NA) return;

    const float2 p   = anc[a];
    const float4 pbx = pboxes[a];
    const float  area1 = (pbx.z - pbx.x) * (pbx.w - pbx.y);
    const float  s0 = scores[a];

    unsigned long long mask = 0ull;
#pragma unroll
    for (int g = 0; g < NG; ++g) {
        float4 bx = s_gt[g];
        bool in = (p.x >= bx.x) && (p.x <= bx.z) && (p.y >= bx.y) && (p.y <= bx.w);
        if (in) mask |= (1ull << g);
    }

    float best = 0.f;
    int bestg = 0;                         // argmax of an all-zero row -> 0
    while (mask) {
        const int g = __ffsll((long long)mask) - 1;   // ascending g: first-max tie rule
        mask &= mask - 1ull;
        const float4 bx = s_gt[g];
        float lx = fmaxf(pbx.x, bx.x);
        float ly = fmaxf(pbx.y, bx.y);
        float rx = fminf(pbx.z, bx.z);
        float ry = fminf(pbx.w, bx.w);
        float w  = fmaxf(rx - lx, 0.f);
        float h  = fmaxf(ry - ly, 0.f);
        float inter = w * h;
        float iou = inter / (area1 + s_area[g] - inter);
        float i2  = iou * iou;
        float v   = s0 * (i2 * i2 * i2);   // cls^1 * iou^6
        if (v > best) { best = v; bestg = g; }
        if (v > 0.f) {
            int pos = atomicAdd(&g_count[g], 1);
            if (pos < CAP) {
                g_val[g * CAP + pos] = v;
                g_anc[g * CAP + pos] = a;
            }
        }
    }
    g_best[a] = bestg;
    g_fg[a]   = 0;                         // reset for K3
}

// K2: one block per GT -> 10th-largest candidate value becomes the threshold.
__global__ void __launch_bounds__(TBS) k_thresh() {
    const int g   = blockIdx.x;
    const int c   = min(g_count[g], CAP);
    const int tid = threadIdx.x;

    float t[TOPK];
#pragma unroll
    for (int i = 0; i < TOPK; ++i) t[i] = 0.f;

    for (int i = tid; i < c; i += TBS) {
        float v = g_val[g * CAP + i];
        if (v > t[0]) {
            t[0] = v;
#pragma unroll
            for (int k = 0; k < TOPK - 1; ++k) {
                if (t[k] > t[k + 1]) { float tmp = t[k]; t[k] = t[k + 1]; t[k + 1] = tmp; }
                else break;
            }
        }
    }

    __shared__ float sv[TBS * TOPK];
#pragma unroll
    for (int i = 0; i < TOPK; ++i) sv[tid * TOPK + i] = t[i];
    __syncthreads();

    for (int stride = TBS / 2; stride >= 1; stride >>= 1) {
        if (tid < stride) {
            float o[TOPK];
#pragma unroll
            for (int i = 0; i < TOPK; ++i) o[i] = sv[(tid + stride) * TOPK + i];
            float m[TOPK];
            int ti = TOPK - 1, oi = TOPK - 1;
#pragma unroll
            for (int k = TOPK - 1; k >= 0; --k) {
                float tv = (ti >= 0) ? t[ti] : -1.f;
                float ov = (oi >= 0) ? o[oi] : -1.f;
                if (tv >= ov) { m[k] = tv; --ti; }
                else          { m[k] = ov; --oi; }
            }
#pragma unroll
            for (int i = 0; i < TOPK; ++i) { t[i] = m[i]; sv[tid * TOPK + i] = m[i]; }
        }
        __syncthreads();
    }
    if (tid == 0) g_thresh[g] = t[0];      // 10th largest (0 if fewer than 10 positives)
}

// K3: mark fg anchors (all stored candidates are > 0, so >= thresh is the top-k set).
__global__ void __launch_bounds__(TBS) k_mark() {
    const int g = blockIdx.y;
    const int c = min(g_count[g], CAP);
    const float th = g_thresh[g];
    for (int i = blockIdx.x * blockDim.x + threadIdx.x; i < c;
         i += gridDim.x * blockDim.x) {
        if (g_val[g * CAP + i] >= th) g_fg[g_anc[g * CAP + i]] = 1;
    }
}

// K4: float32 output. out[0..A) = fg_mask as 0.0/1.0, out[A..2A) = argmax idx.
__global__ void __launch_bounds__(TBS) k_final(float* __restrict__ out, int write_idx) {
    const int a = blockIdx.x * blockDim.x + threadIdx.x;
    if (a >= NA) return;
    const int fg = g_fg[a];
    out[a] = fg ? 1.0f : 0.0f;
    if (write_idx) out[NA + a] = (float)(fg ? g_best[a] : 0);
}

extern "C" void kernel_launch(void* const* d_in, const int* in_sizes, int n_in,
                              void* d_out, int out_size) {
    // Bind inputs BY ELEMENT COUNT on the host — the five sizes are pairwise
    // distinct (400000 / 1600000 / 800000 / 64 / 256), so this is ordering-proof
    // and costs zero device work (the 246us run proved binding was never the
    // failure; the single-threaded device-side sniffer was pure overhead).
    const float*  scores = nullptr;
    const float4* pboxes = nullptr;
    const float2* anc    = nullptr;
    const float4* gtb    = nullptr;
    for (int i = 0; i < n_in; ++i) {
        switch (in_sizes[i]) {
            case NA:     scores = (const float*)d_in[i];  break;
            case NA * 4: pboxes = (const float4*)d_in[i]; break;
            case NA * 2: anc    = (const float2*)d_in[i]; break;
            case NG * 4: gtb    = (const float4*)d_in[i]; break;
            default: break;   // gt_labels (NG) unused: NUM_CLASSES == 1
        }
    }
    const int write_idx = (out_size >= 2 * NA) ? 1 : 0;

    k_zero  <<<1, 64>>>();
    k_main  <<<(NA + TBS - 1) / TBS, TBS>>>(scores, pboxes, anc, gtb);
    k_thresh<<<NG, TBS>>>();
    k_mark  <<<dim3(8, NG), TBS>>>();
    k_final <<<(NA + TBS - 1) / TBS, TBS>>>((float*)d_out, write_idx);
}